// round 16
// baseline (speedup 1.0000x reference)
#include <cuda_runtime.h>
#include <cuda_bf16.h>
#include <cstdint>
#include <cstddef>

#define NMAX 50000
#define EMAX 800000
#define DF   128
#define NC   64

// ---------------- scratch (static device globals; no allocation) -------------
__device__ float g_dinv[NMAX];
__device__ float g_bufA[(size_t)NMAX * DF];
__device__ float g_bufB[(size_t)NMAX * DF];
__device__ int   g_cnt[NMAX];          // ZERO-INVARIANT: zeroed at tail of launch
__device__ int   g_off[NMAX + 1];
__device__ int   g_cur[NMAX];
__device__ int   g_csr[EMAX];
__device__ int   g_idx64;
// decoupled-lookback scan state
__device__ int            g_blkagg[64];
__device__ int            g_blkpre[64];
__device__ volatile int   g_blkst[64];
// W^T split to bf16 hi/lo, padded layout [n*136 + k] halves: [layer][hi/lo]
__device__ __align__(16) unsigned char g_wt[3][2][128 * 272];

// ---------------- edge utils ---------------------------------------------------
__device__ __forceinline__ int edge_at(const void* e, long long i, int is64) {
    return is64 ? (int)((const long long*)e)[i] : ((const int*)e)[i];
}

// ------- W prep + edge dtype detect --------------------------------------------
__global__ void k_prepw(const void* edges,
                        const float* __restrict__ W1,
                        const float* __restrict__ W2,
                        const float* __restrict__ W3) {
    int i = blockIdx.x * blockDim.x + threadIdx.x;
    if (i == 0) {
        const long long* p = (const long long*)edges;
        int ok = 1;
        #pragma unroll
        for (int j = 0; j < 16; j++) {
            long long v = p[j];
            if (v < 0 || v >= NMAX) ok = 0;
        }
        g_idx64 = ok;
    }
    if (i < 16384 * 2 + 8192) {
        int layer, nout, e;
        const float* W;
        if (i < 16384)      { layer = 0; nout = 128; e = i;         W = W1; }
        else if (i < 32768) { layer = 1; nout = 128; e = i - 16384; W = W2; }
        else                { layer = 2; nout = 64;  e = i - 32768; W = W3; }
        int k = e / nout, nn = e % nout;
        float w = W[k * nout + nn];
        __nv_bfloat16 hi = __float2bfloat16(w);
        __nv_bfloat16 lo = __float2bfloat16(w - __bfloat162float(hi));
        uint32_t off = (uint32_t)(nn * 136 + k) * 2;
        *(__nv_bfloat16*)&g_wt[layer][0][off] = hi;
        *(__nv_bfloat16*)&g_wt[layer][1][off] = lo;
    }
}

// ------- count in-degrees; reset lookback flags ---------------------------------
__global__ void k_count(const void* __restrict__ edges, long long E) {
    long long i = (long long)blockIdx.x * blockDim.x + threadIdx.x;
    if (blockIdx.x == 0 && threadIdx.x < 64) g_blkst[threadIdx.x] = 0;
    if (i < E) atomicAdd(&g_cnt[edge_at(edges, E + i, g_idx64)], 1);
}

// ------- single-kernel exclusive scan (decoupled lookback, 49 blocks) ----------
__global__ void __launch_bounds__(1024) k_scanlb(int n, int E) {
    __shared__ int sm[1024];
    __shared__ int s_base;
    const int t = threadIdx.x;
    const int bid = blockIdx.x;
    const int i = bid * 1024 + t;
    const int v = (i < n) ? g_cnt[i] : 0;
    sm[t] = v;
    __syncthreads();
    #pragma unroll
    for (int o = 1; o < 1024; o <<= 1) {
        int u = (t >= o) ? sm[t - o] : 0;
        __syncthreads();
        sm[t] += u;
        __syncthreads();
    }
    if (t == 0) {
        int agg = sm[1023];
        if (bid == 0) {
            g_blkpre[0] = agg;
            __threadfence();
            g_blkst[0] = 2;
            s_base = 0;
        } else {
            g_blkagg[bid] = agg;
            __threadfence();
            g_blkst[bid] = 1;
            int ex = 0;
            for (int p = bid - 1; p >= 0; ) {
                int st;
                while ((st = g_blkst[p]) == 0) { }
                if (st == 2) { ex += g_blkpre[p]; break; }
                ex += g_blkagg[p];
                p--;
            }
            g_blkpre[bid] = ex + agg;
            __threadfence();
            g_blkst[bid] = 2;
            s_base = ex;
        }
    }
    __syncthreads();
    if (i < n) {
        int incl = sm[t] + s_base;
        int off = incl - v;
        g_off[i] = off;
        g_cur[i] = off;
        g_dinv[i] = rsqrtf((float)(v + 1));   // +1 self loop
        if (i == n - 1) g_off[n] = E;
    }
}

// ------- fill CSR: 4 edges/thread for atomic-latency MLP -----------------------
__global__ void k_fill(const void* __restrict__ edges, long long E) {
    long long base = ((long long)blockIdx.x * blockDim.x + threadIdx.x) * 4;
    int is64 = g_idx64;
    int s[4], d[4], pos[4];
    #pragma unroll
    for (int q = 0; q < 4; q++) {
        long long i = base + q;
        if (i < E) {
            s[q] = edge_at(edges, i, is64);
            d[q] = edge_at(edges, E + i, is64);
        }
    }
    #pragma unroll
    for (int q = 0; q < 4; q++)
        if (base + q < E) pos[q] = atomicAdd(&g_cur[d[q]], 1);
    #pragma unroll
    for (int q = 0; q < 4; q++)
        if (base + q < E) g_csr[pos[q]] = s[q];
}

// ---------------- async copy + MMA helpers --------------------------------------
__device__ __forceinline__ void cpasync16(uint32_t smem_dst, const void* gsrc) {
    asm volatile("cp.async.ca.shared.global [%0], [%1], 16;"
                 :: "r"(smem_dst), "l"(gsrc) : "memory");
}
#define CPASYNC_COMMIT() asm volatile("cp.async.commit_group;" ::: "memory")
#define CPASYNC_WAIT()   asm volatile("cp.async.wait_group 0;" ::: "memory")

__device__ __forceinline__ void lm_x4(uint32_t& r0, uint32_t& r1, uint32_t& r2,
                                      uint32_t& r3, uint32_t a) {
    asm volatile("ldmatrix.sync.aligned.m8n8.x4.shared.b16 {%0,%1,%2,%3}, [%4];"
                 : "=r"(r0), "=r"(r1), "=r"(r2), "=r"(r3) : "r"(a));
}
__device__ __forceinline__ void mma_bf16(float* c, uint32_t a0, uint32_t a1,
                                         uint32_t a2, uint32_t a3,
                                         uint32_t b0, uint32_t b1) {
    asm volatile("mma.sync.aligned.m16n8k16.row.col.f32.bf16.bf16.f32 "
                 "{%0,%1,%2,%3}, {%4,%5,%6,%7}, {%8,%9}, {%0,%1,%2,%3};"
                 : "+f"(c[0]), "+f"(c[1]), "+f"(c[2]), "+f"(c[3])
                 : "r"(a0), "r"(a1), "r"(a2), "r"(a3), "r"(b0), "r"(b1));
}

// W tiles -> smem via cp.async (non-blocking; commit, wait before use)
template<int NOUT>
__device__ __forceinline__ void wcopy_async(char* sm, uint32_t sb, int layer) {
    constexpr int BSZ = NOUT * 272;
    const int t = threadIdx.x;
    const float4* s0 = (const float4*)&g_wt[layer][0][0];
    const float4* s1 = (const float4*)&g_wt[layer][1][0];
    for (int i = t; i < BSZ / 16; i += 512) {
        cpasync16(sb + i * 16, s0 + i);
        cpasync16(sb + BSZ + i * 16, s1 + i);
    }
    CPASYNC_COMMIT();
}

// shared MMA phase: 64-row A tile in smem (hi/lo), B hi/lo in smem -> out
template<int NOUT>
__device__ __forceinline__ void mma_phase(char* sm, uint32_t sb, int row0, int n,
                                          float* __restrict__ out) {
    constexpr int BSZ = NOUT * 272;
    constexpr int A_HI = 2 * BSZ;
    constexpr int A_LO = 2 * BSZ + 64 * 272;
    const int t = threadIdx.x;
    const int warp = t >> 5, lane = t & 31;
    const int rg = (warp >> 2) * 16;
    constexpr int NCH = NOUT / 32;
    constexpr int NP = NCH / 2;
    const int ncq = (warp & 3) * NCH;
    float acc[NCH][4];
    #pragma unroll
    for (int nc = 0; nc < NCH; nc++)
        #pragma unroll
        for (int q = 0; q < 4; q++) acc[nc][q] = 0.f;

    const uint32_t aBase = sb + A_HI
        + (uint32_t)(rg + (lane & 15)) * 272 + (lane >> 4) * 16;
    const uint32_t bBase4 = sb
        + (uint32_t)((ncq + (lane >> 4)) * 8 + (lane & 7)) * 272
        + ((lane >> 3) & 1) * 16;

    #pragma unroll
    for (int kc = 0; kc < 8; kc++) {
        uint32_t ah0, ah1, ah2, ah3, al0, al1, al2, al3;
        lm_x4(ah0, ah1, ah2, ah3, aBase + kc * 32);
        lm_x4(al0, al1, al2, al3, aBase + (A_LO - A_HI) + kc * 32);
        #pragma unroll
        for (int p = 0; p < NP; p++) {
            uint32_t bh0, bh1, bh2, bh3, bl0, bl1, bl2, bl3;
            uint32_t ba = bBase4 + (uint32_t)p * 4352 + kc * 32;  // 2*8*272=4352
            lm_x4(bh0, bh1, bh2, bh3, ba);
            lm_x4(bl0, bl1, bl2, bl3, ba + BSZ);
            mma_bf16(acc[2 * p],     ah0, ah1, ah2, ah3, bh0, bh1);
            mma_bf16(acc[2 * p],     ah0, ah1, ah2, ah3, bl0, bl1);
            mma_bf16(acc[2 * p],     al0, al1, al2, al3, bh0, bh1);
            mma_bf16(acc[2 * p + 1], ah0, ah1, ah2, ah3, bh2, bh3);
            mma_bf16(acc[2 * p + 1], ah0, ah1, ah2, ah3, bl2, bl3);
            mma_bf16(acc[2 * p + 1], al0, al1, al2, al3, bh2, bh3);
        }
    }

    const int r0 = row0 + rg + (lane >> 2);
    const int r1 = r0 + 8;
    const int cb = ncq * 8 + (lane & 3) * 2;
    const float dv0 = (r0 < n) ? g_dinv[r0] : 0.f;
    const float dv1 = (r1 < n) ? g_dinv[r1] : 0.f;
    #pragma unroll
    for (int nc = 0; nc < NCH; nc++) {
        int col = cb + nc * 8;
        if (r0 < n) {
            float2 o; o.x = dv0 * acc[nc][0]; o.y = dv0 * acc[nc][1];
            *(float2*)(out + (size_t)r0 * NOUT + col) = o;
        }
        if (r1 < n) {
            float2 o; o.x = dv1 * acc[nc][2]; o.y = dv1 * acc[nc][3];
            *(float2*)(out + (size_t)r1 * NOUT + col) = o;
        }
    }
}

// helper: split float4 to bf16 hi/lo and store at smem row offset
__device__ __forceinline__ void split_store(char* ah, char* al, float4 v) {
    __nv_bfloat162 h0, h1, l0, l1;
    h0.x = __float2bfloat16(v.x); h0.y = __float2bfloat16(v.y);
    h1.x = __float2bfloat16(v.z); h1.y = __float2bfloat16(v.w);
    l0.x = __float2bfloat16(v.x - __bfloat162float(h0.x));
    l0.y = __float2bfloat16(v.y - __bfloat162float(h0.y));
    l1.x = __float2bfloat16(v.z - __bfloat162float(h1.x));
    l1.y = __float2bfloat16(v.w - __bfloat162float(h1.y));
    *(__nv_bfloat162*)(ah)     = h0;
    *(__nv_bfloat162*)(ah + 4) = h1;
    *(__nv_bfloat162*)(al)     = l0;
    *(__nv_bfloat162*)(al + 4) = l1;
}

// ------------- persistent layer-1 GEMM: out[r] = dinv[r]*(X@W)[r] --------------
template<int NOUT, bool RELU>
__global__ void __launch_bounds__(512, 2) k_hgemm(const float* __restrict__ X,
                                                  float* __restrict__ out,
                                                  int layer, int n) {
    extern __shared__ char sm[];
    constexpr int BSZ = NOUT * 272;
    constexpr int A_HI = 2 * BSZ;
    constexpr int A_LO = 2 * BSZ + 64 * 272;
    const int t = threadIdx.x;
    const int ntiles = (n + 63) >> 6;

    uint32_t sb;
    asm("{ .reg .u64 u; cvta.to.shared.u64 u, %1; cvt.u32.u64 %0, u; }"
        : "=r"(sb) : "l"(sm));

    wcopy_async<NOUT>(sm, sb, layer);   // W once per persistent block
    bool first = true;

    for (int tile = blockIdx.x; tile < ntiles; tile += gridDim.x) {
        const int row0 = tile * 64;
        {
            const int row = t >> 3;
            const int c0 = (t & 7) * 16;
            const int gr = row0 + row;
            const float4* xr = (const float4*)(X + (size_t)gr * 128 + c0);
            char* ah = sm + A_HI + row * 272 + c0 * 2;
            char* al = sm + A_LO + row * 272 + c0 * 2;
            #pragma unroll
            for (int q = 0; q < 4; q++) {
                float4 v = (gr < n) ? xr[q] : make_float4(0.f, 0.f, 0.f, 0.f);
                if (RELU) {
                    v.x = fmaxf(v.x, 0.f); v.y = fmaxf(v.y, 0.f);
                    v.z = fmaxf(v.z, 0.f); v.w = fmaxf(v.w, 0.f);
                }
                split_store(ah + q * 8, al + q * 8, v);
            }
        }
        if (first) { CPASYNC_WAIT(); first = false; }
        __syncthreads();
        mma_phase<NOUT>(sm, sb, row0, n, out);
        __syncthreads();
    }
}

// ------------- persistent FUSED: gather layer-i (e out) + GEMM layer-(i+1) -----
template<int NOUT>
__global__ void __launch_bounds__(512, 2) k_fusedg(
    const float* __restrict__ bufin, float* __restrict__ bufout,
    const float* __restrict__ bias, float* __restrict__ e_out,
    int layer, int n) {
    extern __shared__ char sm[];
    constexpr int BSZ = NOUT * 272;
    constexpr int A_HI = 2 * BSZ;
    constexpr int A_LO = 2 * BSZ + 64 * 272;
    const int t = threadIdx.x;
    const int ntiles = (n + 63) >> 6;

    uint32_t sb;
    asm("{ .reg .u64 u; cvta.to.shared.u64 u, %1; cvt.u32.u64 %0, u; }"
        : "=r"(sb) : "l"(sm));

    wcopy_async<NOUT>(sm, sb, layer);   // W once per persistent block
    bool first = true;

    const int warp = t >> 5, lane = t & 31;
    float4 bb = *(const float4*)(bias + lane * 4);

    for (int tile = blockIdx.x; tile < ntiles; tile += gridDim.x) {
        const int row0 = tile * 64;
        #pragma unroll
        for (int i = 0; i < 4; i++) {
            int r = row0 + warp * 4 + i;
            int rr = warp * 4 + i;
            char* ah = sm + A_HI + rr * 272 + lane * 8;
            char* al = sm + A_LO + rr * 272 + lane * 8;
            if (r < n) {
                int j = g_off[r], end = g_off[r + 1];
                float dd = g_dinv[r];
                float4 a0 = *(const float4*)(bufin + (size_t)r * 128 + lane * 4);
                float4 a1 = make_float4(0.f, 0.f, 0.f, 0.f);
                float4 a2 = make_float4(0.f, 0.f, 0.f, 0.f);
                float4 a3 = make_float4(0.f, 0.f, 0.f, 0.f);
                for (; j + 4 <= end; j += 4) {
                    int s0 = __ldg(&g_csr[j]);
                    int s1 = __ldg(&g_csr[j + 1]);
                    int s2 = __ldg(&g_csr[j + 2]);
                    int s3 = __ldg(&g_csr[j + 3]);
                    float4 v0 = *(const float4*)(bufin + (size_t)s0 * 128 + lane * 4);
                    float4 v1 = *(const float4*)(bufin + (size_t)s1 * 128 + lane * 4);
                    float4 v2 = *(const float4*)(bufin + (size_t)s2 * 128 + lane * 4);
                    float4 v3 = *(const float4*)(bufin + (size_t)s3 * 128 + lane * 4);
                    a0.x += v0.x; a0.y += v0.y; a0.z += v0.z; a0.w += v0.w;
                    a1.x += v1.x; a1.y += v1.y; a1.z += v1.z; a1.w += v1.w;
                    a2.x += v2.x; a2.y += v2.y; a2.z += v2.z; a2.w += v2.w;
                    a3.x += v3.x; a3.y += v3.y; a3.z += v3.z; a3.w += v3.w;
                }
                for (; j < end; j++) {
                    int s0 = __ldg(&g_csr[j]);
                    float4 v0 = *(const float4*)(bufin + (size_t)s0 * 128 + lane * 4);
                    a0.x += v0.x; a0.y += v0.y; a0.z += v0.z; a0.w += v0.w;
                }
                a0.x += a1.x + a2.x + a3.x;
                a0.y += a1.y + a2.y + a3.y;
                a0.z += a1.z + a2.z + a3.z;
                a0.w += a1.w + a2.w + a3.w;
                float4 e;
                e.x = fmaf(dd, a0.x, bb.x); e.y = fmaf(dd, a0.y, bb.y);
                e.z = fmaf(dd, a0.z, bb.z); e.w = fmaf(dd, a0.w, bb.w);
                *(float4*)(e_out + (size_t)r * 128 + lane * 4) = e;
                e.x = fmaxf(e.x, 0.f); e.y = fmaxf(e.y, 0.f);
                e.z = fmaxf(e.z, 0.f); e.w = fmaxf(e.w, 0.f);
                split_store(ah, al, e);
            } else {
                split_store(ah, al, make_float4(0.f, 0.f, 0.f, 0.f));
            }
        }
        if (first) { CPASYNC_WAIT(); first = false; }
        __syncthreads();
        mma_phase<NOUT>(sm, sb, row0, n, bufout);
        __syncthreads();
    }
}

// ---------------- final gather (64-wide) + log_softmax -------------------------
__global__ void k_gather64_lsm(const float* __restrict__ bufin,
                               const float* __restrict__ bias,
                               float* __restrict__ e3,
                               float* __restrict__ logp, int n) {
    // tail duty: restore the g_cnt zero-invariant for the next replay
    {
        int gi = blockIdx.x * blockDim.x + threadIdx.x;
        if (gi < NMAX) g_cnt[gi] = 0;
    }
    int w = (blockIdx.x * blockDim.x + threadIdx.x) >> 5;
    int lane = threadIdx.x & 31;
    if (w >= n) return;
    int j = g_off[w], end = g_off[w + 1];
    float dd = g_dinv[w];
    float2 a0 = *(const float2*)(bufin + (size_t)w * 64 + lane * 2);
    float2 a1 = make_float2(0.f, 0.f);
    float2 a2 = make_float2(0.f, 0.f);
    float2 a3 = make_float2(0.f, 0.f);
    for (; j + 4 <= end; j += 4) {
        int s0 = __ldg(&g_csr[j]);
        int s1 = __ldg(&g_csr[j + 1]);
        int s2 = __ldg(&g_csr[j + 2]);
        int s3 = __ldg(&g_csr[j + 3]);
        float2 v0 = *(const float2*)(bufin + (size_t)s0 * 64 + lane * 2);
        float2 v1 = *(const float2*)(bufin + (size_t)s1 * 64 + lane * 2);
        float2 v2 = *(const float2*)(bufin + (size_t)s2 * 64 + lane * 2);
        float2 v3 = *(const float2*)(bufin + (size_t)s3 * 64 + lane * 2);
        a0.x += v0.x; a0.y += v0.y;
        a1.x += v1.x; a1.y += v1.y;
        a2.x += v2.x; a2.y += v2.y;
        a3.x += v3.x; a3.y += v3.y;
    }
    for (; j < end; j++) {
        int s0 = __ldg(&g_csr[j]);
        float2 v0 = *(const float2*)(bufin + (size_t)s0 * 64 + lane * 2);
        a0.x += v0.x; a0.y += v0.y;
    }
    a0.x += a1.x + a2.x + a3.x;
    a0.y += a1.y + a2.y + a3.y;
    float2 bb = *(const float2*)(bias + lane * 2);
    float r0 = fmaf(dd, a0.x, bb.x);
    float r1 = fmaf(dd, a0.y, bb.y);
    float2 ev; ev.x = r0; ev.y = r1;
    *(float2*)(e3 + (size_t)w * 64 + lane * 2) = ev;
    float mx = fmaxf(r0, r1);
    #pragma unroll
    for (int o = 16; o; o >>= 1) mx = fmaxf(mx, __shfl_xor_sync(0xffffffffu, mx, o));
    float sum = expf(r0 - mx) + expf(r1 - mx);
    #pragma unroll
    for (int o = 16; o; o >>= 1) sum += __shfl_xor_sync(0xffffffffu, sum, o);
    float lz = mx + logf(sum);
    float2 lp; lp.x = r0 - lz; lp.y = r1 - lz;
    *(float2*)(logp + (size_t)w * 64 + lane * 2) = lp;
}

// ---------------- launcher ------------------------------------------------------
extern "C" void kernel_launch(void* const* d_in, const int* in_sizes, int n_in,
                              void* d_out, int out_size) {
    const float* x  = (const float*)d_in[0];
    const void*  ed = d_in[1];
    const float* W1 = (const float*)d_in[2];
    const float* b1 = (const float*)d_in[3];
    const float* W2 = (const float*)d_in[4];
    const float* b2 = (const float*)d_in[5];
    const float* W3 = (const float*)d_in[6];
    const float* b3 = (const float*)d_in[7];

    int       N = in_sizes[0] / DF;
    long long E = (long long)in_sizes[1] / 2;

    float* out  = (float*)d_out;
    float* logp = out;
    float* e1   = out + (size_t)N * NC;
    float* e2   = e1 + (size_t)N * DF;
    float* e3   = e2 + (size_t)N * DF;

    float* bufA; cudaGetSymbolAddress((void**)&bufA, g_bufA);
    float* bufB; cudaGetSymbolAddress((void**)&bufB, g_bufB);

    const int smem128 = 2 * 128 * 272 + 2 * 64 * 272;  // 104448 -> 2 CTAs/SM
    const int smem64  = 2 * 64 * 272 + 2 * 64 * 272;   //  69632
    cudaFuncSetAttribute((const void*)k_hgemm<128, false>,
                         cudaFuncAttributeMaxDynamicSharedMemorySize, smem128);
    cudaFuncSetAttribute((const void*)k_fusedg<128>,
                         cudaFuncAttributeMaxDynamicSharedMemorySize, smem128);
    cudaFuncSetAttribute((const void*)k_fusedg<64>,
                         cudaFuncAttributeMaxDynamicSharedMemorySize, smem64);

    int nb_prep  = (16384 * 2 + 8192 + 255) / 256;
    int nb_edges = (int)((E + 255) / 256);
    int nb_fill  = (int)((E + 1023) / 1024);
    int nb_scan  = (N + 1023) / 1024;
    int nb_pers  = 296;                    // 148 SMs x 2 CTAs, persistent
    int nb_tiles = (N + 63) / 64;
    if (nb_pers > nb_tiles) nb_pers = nb_tiles;
    int nb_gat   = (N + 7) / 8;

    // ---- CSR build + W prep; hgemm1 hoisted before fill (independent) ----
    k_prepw<<<nb_prep, 256>>>(ed, W1, W2, W3);
    k_count<<<nb_edges, 256>>>(ed, E);
    k_scanlb<<<nb_scan, 1024>>>(N, (int)E);
    k_hgemm<128, false><<<nb_pers, 512, smem128>>>(x, bufA, 0, N);  // profile slot
    k_fill<<<nb_fill, 256>>>(ed, E);

    // ---- fused: gather1 (e1) + gemm W2 -> bufB ----
    k_fusedg<128><<<nb_pers, 512, smem128>>>(bufA, bufB, b1, e1, 1, N);

    // ---- fused: gather2 (e2) + gemm W3 -> bufA (64-wide) ----
    k_fusedg<64><<<nb_pers, 512, smem64>>>(bufB, bufA, b2, e2, 2, N);

    // ---- final gather + log_softmax ----
    k_gather64_lsm<<<nb_gat, 256>>>(bufA, b3, e3, logp, N);
}

// round 17
// speedup vs baseline: 1.0190x; 1.0190x over previous
#include <cuda_runtime.h>
#include <cuda_bf16.h>
#include <cstdint>
#include <cstddef>

#define NMAX 50000
#define EMAX 800000
#define DF   128
#define NC   64

// ---------------- scratch (static device globals; no allocation) -------------
__device__ float g_dinv[NMAX];
__device__ float g_bufA[(size_t)NMAX * DF];
__device__ float g_bufB[(size_t)NMAX * DF];
__device__ int   g_cnt[NMAX];          // ZERO-INVARIANT: zeroed at tail of launch
__device__ int   g_off[NMAX + 1];
__device__ int   g_cur[NMAX];
__device__ int   g_csr[EMAX];
__device__ int   g_idx64;
// decoupled-lookback scan state
__device__ int            g_blkagg[64];
__device__ int            g_blkpre[64];
__device__ volatile int   g_blkst[64];
// W^T split to bf16 hi/lo, padded layout [n*136 + k] halves: [layer][hi/lo]
__device__ __align__(16) unsigned char g_wt[3][2][128 * 272];

// ---------------- edge utils ---------------------------------------------------
__device__ __forceinline__ int edge_at(const void* e, long long i, int is64) {
    return is64 ? (int)((const long long*)e)[i] : ((const int*)e)[i];
}

// ------- W prep + edge dtype detect --------------------------------------------
__global__ void k_prepw(const void* edges,
                        const float* __restrict__ W1,
                        const float* __restrict__ W2,
                        const float* __restrict__ W3) {
    int i = blockIdx.x * blockDim.x + threadIdx.x;
    if (i == 0) {
        const long long* p = (const long long*)edges;
        int ok = 1;
        #pragma unroll
        for (int j = 0; j < 16; j++) {
            long long v = p[j];
            if (v < 0 || v >= NMAX) ok = 0;
        }
        g_idx64 = ok;
    }
    if (i < 16384 * 2 + 8192) {
        int layer, nout, e;
        const float* W;
        if (i < 16384)      { layer = 0; nout = 128; e = i;         W = W1; }
        else if (i < 32768) { layer = 1; nout = 128; e = i - 16384; W = W2; }
        else                { layer = 2; nout = 64;  e = i - 32768; W = W3; }
        int k = e / nout, nn = e % nout;
        float w = W[k * nout + nn];
        __nv_bfloat16 hi = __float2bfloat16(w);
        __nv_bfloat16 lo = __float2bfloat16(w - __bfloat162float(hi));
        uint32_t off = (uint32_t)(nn * 136 + k) * 2;
        *(__nv_bfloat16*)&g_wt[layer][0][off] = hi;
        *(__nv_bfloat16*)&g_wt[layer][1][off] = lo;
    }
}

// ------- count in-degrees; reset lookback flags ---------------------------------
__global__ void k_count(const void* __restrict__ edges, long long E) {
    long long i = (long long)blockIdx.x * blockDim.x + threadIdx.x;
    if (blockIdx.x == 0 && threadIdx.x < 64) g_blkst[threadIdx.x] = 0;
    if (i < E) atomicAdd(&g_cnt[edge_at(edges, E + i, g_idx64)], 1);
}

// ------- single-kernel exclusive scan (decoupled lookback, 49 blocks) ----------
__global__ void __launch_bounds__(1024) k_scanlb(int n, int E) {
    __shared__ int sm[1024];
    __shared__ int s_base;
    const int t = threadIdx.x;
    const int bid = blockIdx.x;
    const int i = bid * 1024 + t;
    const int v = (i < n) ? g_cnt[i] : 0;
    sm[t] = v;
    __syncthreads();
    #pragma unroll
    for (int o = 1; o < 1024; o <<= 1) {
        int u = (t >= o) ? sm[t - o] : 0;
        __syncthreads();
        sm[t] += u;
        __syncthreads();
    }
    if (t == 0) {
        int agg = sm[1023];
        if (bid == 0) {
            g_blkpre[0] = agg;
            __threadfence();
            g_blkst[0] = 2;
            s_base = 0;
        } else {
            g_blkagg[bid] = agg;
            __threadfence();
            g_blkst[bid] = 1;
            int ex = 0;
            for (int p = bid - 1; p >= 0; ) {
                int st;
                while ((st = g_blkst[p]) == 0) { }
                if (st == 2) { ex += g_blkpre[p]; break; }
                ex += g_blkagg[p];
                p--;
            }
            g_blkpre[bid] = ex + agg;
            __threadfence();
            g_blkst[bid] = 2;
            s_base = ex;
        }
    }
    __syncthreads();
    if (i < n) {
        int incl = sm[t] + s_base;
        int off = incl - v;
        g_off[i] = off;
        g_cur[i] = off;
        g_dinv[i] = rsqrtf((float)(v + 1));   // +1 self loop
        if (i == n - 1) g_off[n] = E;
    }
}

// ------- fill CSR: 4 edges/thread for atomic-latency MLP -----------------------
__global__ void k_fill(const void* __restrict__ edges, long long E) {
    long long base = ((long long)blockIdx.x * blockDim.x + threadIdx.x) * 4;
    int is64 = g_idx64;
    int s[4], d[4], pos[4];
    #pragma unroll
    for (int q = 0; q < 4; q++) {
        long long i = base + q;
        if (i < E) {
            s[q] = edge_at(edges, i, is64);
            d[q] = edge_at(edges, E + i, is64);
        }
    }
    #pragma unroll
    for (int q = 0; q < 4; q++)
        if (base + q < E) pos[q] = atomicAdd(&g_cur[d[q]], 1);
    #pragma unroll
    for (int q = 0; q < 4; q++)
        if (base + q < E) g_csr[pos[q]] = s[q];
}

// ---------------- async copy + MMA helpers --------------------------------------
__device__ __forceinline__ void cpasync16(uint32_t smem_dst, const void* gsrc) {
    asm volatile("cp.async.ca.shared.global [%0], [%1], 16;"
                 :: "r"(smem_dst), "l"(gsrc) : "memory");
}
#define CPASYNC_COMMIT() asm volatile("cp.async.commit_group;" ::: "memory")
#define CPASYNC_WAIT()   asm volatile("cp.async.wait_group 0;" ::: "memory")

__device__ __forceinline__ void lm_x4(uint32_t& r0, uint32_t& r1, uint32_t& r2,
                                      uint32_t& r3, uint32_t a) {
    asm volatile("ldmatrix.sync.aligned.m8n8.x4.shared.b16 {%0,%1,%2,%3}, [%4];"
                 : "=r"(r0), "=r"(r1), "=r"(r2), "=r"(r3) : "r"(a));
}
__device__ __forceinline__ void mma_bf16(float* c, uint32_t a0, uint32_t a1,
                                         uint32_t a2, uint32_t a3,
                                         uint32_t b0, uint32_t b1) {
    asm volatile("mma.sync.aligned.m16n8k16.row.col.f32.bf16.bf16.f32 "
                 "{%0,%1,%2,%3}, {%4,%5,%6,%7}, {%8,%9}, {%0,%1,%2,%3};"
                 : "+f"(c[0]), "+f"(c[1]), "+f"(c[2]), "+f"(c[3])
                 : "r"(a0), "r"(a1), "r"(a2), "r"(a3), "r"(b0), "r"(b1));
}

// W tiles -> smem via cp.async (non-blocking; commit, wait before use)
template<int NOUT>
__device__ __forceinline__ void wcopy_async(char* sm, uint32_t sb, int layer) {
    constexpr int BSZ = NOUT * 272;
    const int t = threadIdx.x;
    const float4* s0 = (const float4*)&g_wt[layer][0][0];
    const float4* s1 = (const float4*)&g_wt[layer][1][0];
    for (int i = t; i < BSZ / 16; i += 512) {
        cpasync16(sb + i * 16, s0 + i);
        cpasync16(sb + BSZ + i * 16, s1 + i);
    }
    CPASYNC_COMMIT();
}

// shared MMA phase: 64-row A tile in smem (hi/lo), B hi/lo in smem -> out
template<int NOUT>
__device__ __forceinline__ void mma_phase(char* sm, uint32_t sb, int row0, int n,
                                          float* __restrict__ out) {
    constexpr int BSZ = NOUT * 272;
    constexpr int A_HI = 2 * BSZ;
    constexpr int A_LO = 2 * BSZ + 64 * 272;
    const int t = threadIdx.x;
    const int warp = t >> 5, lane = t & 31;
    const int rg = (warp >> 2) * 16;
    constexpr int NCH = NOUT / 32;
    constexpr int NP = NCH / 2;
    const int ncq = (warp & 3) * NCH;
    float acc[NCH][4];
    #pragma unroll
    for (int nc = 0; nc < NCH; nc++)
        #pragma unroll
        for (int q = 0; q < 4; q++) acc[nc][q] = 0.f;

    const uint32_t aBase = sb + A_HI
        + (uint32_t)(rg + (lane & 15)) * 272 + (lane >> 4) * 16;
    const uint32_t bBase4 = sb
        + (uint32_t)((ncq + (lane >> 4)) * 8 + (lane & 7)) * 272
        + ((lane >> 3) & 1) * 16;

    #pragma unroll
    for (int kc = 0; kc < 8; kc++) {
        uint32_t ah0, ah1, ah2, ah3, al0, al1, al2, al3;
        lm_x4(ah0, ah1, ah2, ah3, aBase + kc * 32);
        lm_x4(al0, al1, al2, al3, aBase + (A_LO - A_HI) + kc * 32);
        #pragma unroll
        for (int p = 0; p < NP; p++) {
            uint32_t bh0, bh1, bh2, bh3, bl0, bl1, bl2, bl3;
            uint32_t ba = bBase4 + (uint32_t)p * 4352 + kc * 32;  // 2*8*272=4352
            lm_x4(bh0, bh1, bh2, bh3, ba);
            lm_x4(bl0, bl1, bl2, bl3, ba + BSZ);
            mma_bf16(acc[2 * p],     ah0, ah1, ah2, ah3, bh0, bh1);
            mma_bf16(acc[2 * p],     ah0, ah1, ah2, ah3, bl0, bl1);
            mma_bf16(acc[2 * p],     al0, al1, al2, al3, bh0, bh1);
            mma_bf16(acc[2 * p + 1], ah0, ah1, ah2, ah3, bh2, bh3);
            mma_bf16(acc[2 * p + 1], ah0, ah1, ah2, ah3, bl2, bl3);
            mma_bf16(acc[2 * p + 1], al0, al1, al2, al3, bh2, bh3);
        }
    }

    const int r0 = row0 + rg + (lane >> 2);
    const int r1 = r0 + 8;
    const int cb = ncq * 8 + (lane & 3) * 2;
    const float dv0 = (r0 < n) ? g_dinv[r0] : 0.f;
    const float dv1 = (r1 < n) ? g_dinv[r1] : 0.f;
    #pragma unroll
    for (int nc = 0; nc < NCH; nc++) {
        int col = cb + nc * 8;
        if (r0 < n) {
            float2 o; o.x = dv0 * acc[nc][0]; o.y = dv0 * acc[nc][1];
            *(float2*)(out + (size_t)r0 * NOUT + col) = o;
        }
        if (r1 < n) {
            float2 o; o.x = dv1 * acc[nc][2]; o.y = dv1 * acc[nc][3];
            *(float2*)(out + (size_t)r1 * NOUT + col) = o;
        }
    }
}

// helper: split float4 to bf16 hi/lo and store at smem row offset
__device__ __forceinline__ void split_store(char* ah, char* al, float4 v) {
    __nv_bfloat162 h0, h1, l0, l1;
    h0.x = __float2bfloat16(v.x); h0.y = __float2bfloat16(v.y);
    h1.x = __float2bfloat16(v.z); h1.y = __float2bfloat16(v.w);
    l0.x = __float2bfloat16(v.x - __bfloat162float(h0.x));
    l0.y = __float2bfloat16(v.y - __bfloat162float(h0.y));
    l1.x = __float2bfloat16(v.z - __bfloat162float(h1.x));
    l1.y = __float2bfloat16(v.w - __bfloat162float(h1.y));
    *(__nv_bfloat162*)(ah)     = h0;
    *(__nv_bfloat162*)(ah + 4) = h1;
    *(__nv_bfloat162*)(al)     = l0;
    *(__nv_bfloat162*)(al + 4) = l1;
}

// ------------- layer-1 GEMM: out[r] = dinv[r] * (X @ W1)[r] --------------------
template<int NOUT, bool RELU>
__global__ void __launch_bounds__(512, 2) k_hgemm(const float* __restrict__ X,
                                                  float* __restrict__ out,
                                                  int layer, int n) {
    extern __shared__ char sm[];
    constexpr int BSZ = NOUT * 272;
    constexpr int A_HI = 2 * BSZ;
    constexpr int A_LO = 2 * BSZ + 64 * 272;
    const int t = threadIdx.x;
    const int row0 = blockIdx.x * 64;

    uint32_t sb;
    asm("{ .reg .u64 u; cvta.to.shared.u64 u, %1; cvt.u32.u64 %0, u; }"
        : "=r"(sb) : "l"(sm));

    wcopy_async<NOUT>(sm, sb, layer);   // W streams in under the A phase

    {
        const int row = t >> 3;
        const int c0 = (t & 7) * 16;
        const int gr = row0 + row;
        const float4* xr = (const float4*)(X + (size_t)gr * 128 + c0);
        char* ah = sm + A_HI + row * 272 + c0 * 2;
        char* al = sm + A_LO + row * 272 + c0 * 2;
        #pragma unroll
        for (int q = 0; q < 4; q++) {
            float4 v = (gr < n) ? xr[q] : make_float4(0.f, 0.f, 0.f, 0.f);
            if (RELU) {
                v.x = fmaxf(v.x, 0.f); v.y = fmaxf(v.y, 0.f);
                v.z = fmaxf(v.z, 0.f); v.w = fmaxf(v.w, 0.f);
            }
            split_store(ah + q * 8, al + q * 8, v);
        }
    }
    CPASYNC_WAIT();
    __syncthreads();
    mma_phase<NOUT>(sm, sb, row0, n, out);
}

// ------------- FUSED: gather layer-i (e out) + GEMM layer-(i+1) ----------------
// gather inner loop: 8 independent row loads in flight (MLP 8).
template<int NOUT>
__global__ void __launch_bounds__(512, 2) k_fusedg(
    const float* __restrict__ bufin, float* __restrict__ bufout,
    const float* __restrict__ bias, float* __restrict__ e_out,
    int layer, int n) {
    extern __shared__ char sm[];
    constexpr int BSZ = NOUT * 272;
    constexpr int A_HI = 2 * BSZ;
    constexpr int A_LO = 2 * BSZ + 64 * 272;
    const int t = threadIdx.x;
    const int row0 = blockIdx.x * 64;

    uint32_t sb;
    asm("{ .reg .u64 u; cvta.to.shared.u64 u, %1; cvt.u32.u64 %0, u; }"
        : "=r"(sb) : "l"(sm));

    wcopy_async<NOUT>(sm, sb, layer);   // W streams in under the gather phase

    {
        const int warp = t >> 5, lane = t & 31;
        float4 bb = *(const float4*)(bias + lane * 4);
        #pragma unroll
        for (int i = 0; i < 4; i++) {
            int r = row0 + warp * 4 + i;
            int rr = warp * 4 + i;
            char* ah = sm + A_HI + rr * 272 + lane * 8;
            char* al = sm + A_LO + rr * 272 + lane * 8;
            if (r < n) {
                int j = g_off[r], end = g_off[r + 1];
                float dd = g_dinv[r];
                float4 a0 = *(const float4*)(bufin + (size_t)r * 128 + lane * 4);
                float4 a1 = make_float4(0.f, 0.f, 0.f, 0.f);
                for (; j + 8 <= end; j += 8) {
                    int s0 = __ldg(&g_csr[j]);
                    int s1 = __ldg(&g_csr[j + 1]);
                    int s2 = __ldg(&g_csr[j + 2]);
                    int s3 = __ldg(&g_csr[j + 3]);
                    int s4 = __ldg(&g_csr[j + 4]);
                    int s5 = __ldg(&g_csr[j + 5]);
                    int s6 = __ldg(&g_csr[j + 6]);
                    int s7 = __ldg(&g_csr[j + 7]);
                    float4 v0 = *(const float4*)(bufin + (size_t)s0 * 128 + lane * 4);
                    float4 v1 = *(const float4*)(bufin + (size_t)s1 * 128 + lane * 4);
                    float4 v2 = *(const float4*)(bufin + (size_t)s2 * 128 + lane * 4);
                    float4 v3 = *(const float4*)(bufin + (size_t)s3 * 128 + lane * 4);
                    float4 v4 = *(const float4*)(bufin + (size_t)s4 * 128 + lane * 4);
                    float4 v5 = *(const float4*)(bufin + (size_t)s5 * 128 + lane * 4);
                    float4 v6 = *(const float4*)(bufin + (size_t)s6 * 128 + lane * 4);
                    float4 v7 = *(const float4*)(bufin + (size_t)s7 * 128 + lane * 4);
                    a0.x += v0.x + v2.x + v4.x + v6.x;
                    a0.y += v0.y + v2.y + v4.y + v6.y;
                    a0.z += v0.z + v2.z + v4.z + v6.z;
                    a0.w += v0.w + v2.w + v4.w + v6.w;
                    a1.x += v1.x + v3.x + v5.x + v7.x;
                    a1.y += v1.y + v3.y + v5.y + v7.y;
                    a1.z += v1.z + v3.z + v5.z + v7.z;
                    a1.w += v1.w + v3.w + v5.w + v7.w;
                }
                for (; j + 4 <= end; j += 4) {
                    int s0 = __ldg(&g_csr[j]);
                    int s1 = __ldg(&g_csr[j + 1]);
                    int s2 = __ldg(&g_csr[j + 2]);
                    int s3 = __ldg(&g_csr[j + 3]);
                    float4 v0 = *(const float4*)(bufin + (size_t)s0 * 128 + lane * 4);
                    float4 v1 = *(const float4*)(bufin + (size_t)s1 * 128 + lane * 4);
                    float4 v2 = *(const float4*)(bufin + (size_t)s2 * 128 + lane * 4);
                    float4 v3 = *(const float4*)(bufin + (size_t)s3 * 128 + lane * 4);
                    a0.x += v0.x + v2.x; a0.y += v0.y + v2.y;
                    a0.z += v0.z + v2.z; a0.w += v0.w + v2.w;
                    a1.x += v1.x + v3.x; a1.y += v1.y + v3.y;
                    a1.z += v1.z + v3.z; a1.w += v1.w + v3.w;
                }
                for (; j < end; j++) {
                    int s0 = __ldg(&g_csr[j]);
                    float4 v0 = *(const float4*)(bufin + (size_t)s0 * 128 + lane * 4);
                    a0.x += v0.x; a0.y += v0.y; a0.z += v0.z; a0.w += v0.w;
                }
                a0.x += a1.x; a0.y += a1.y; a0.z += a1.z; a0.w += a1.w;
                float4 e;
                e.x = fmaf(dd, a0.x, bb.x); e.y = fmaf(dd, a0.y, bb.y);
                e.z = fmaf(dd, a0.z, bb.z); e.w = fmaf(dd, a0.w, bb.w);
                *(float4*)(e_out + (size_t)r * 128 + lane * 4) = e;
                e.x = fmaxf(e.x, 0.f); e.y = fmaxf(e.y, 0.f);
                e.z = fmaxf(e.z, 0.f); e.w = fmaxf(e.w, 0.f);
                split_store(ah, al, e);
            } else {
                split_store(ah, al, make_float4(0.f, 0.f, 0.f, 0.f));
            }
        }
    }
    CPASYNC_WAIT();
    __syncthreads();
    mma_phase<NOUT>(sm, sb, row0, n, bufout);
}

// ---------------- final gather (64-wide, MLP 8) + log_softmax ------------------
__global__ void k_gather64_lsm(const float* __restrict__ bufin,
                               const float* __restrict__ bias,
                               float* __restrict__ e3,
                               float* __restrict__ logp, int n) {
    // tail duty: restore the g_cnt zero-invariant for the next replay
    {
        int gi = blockIdx.x * blockDim.x + threadIdx.x;
        if (gi < NMAX) g_cnt[gi] = 0;
    }
    int w = (blockIdx.x * blockDim.x + threadIdx.x) >> 5;
    int lane = threadIdx.x & 31;
    if (w >= n) return;
    int j = g_off[w], end = g_off[w + 1];
    float dd = g_dinv[w];
    float2 a0 = *(const float2*)(bufin + (size_t)w * 64 + lane * 2);
    float2 a1 = make_float2(0.f, 0.f);
    for (; j + 8 <= end; j += 8) {
        int s0 = __ldg(&g_csr[j]);
        int s1 = __ldg(&g_csr[j + 1]);
        int s2 = __ldg(&g_csr[j + 2]);
        int s3 = __ldg(&g_csr[j + 3]);
        int s4 = __ldg(&g_csr[j + 4]);
        int s5 = __ldg(&g_csr[j + 5]);
        int s6 = __ldg(&g_csr[j + 6]);
        int s7 = __ldg(&g_csr[j + 7]);
        float2 v0 = *(const float2*)(bufin + (size_t)s0 * 64 + lane * 2);
        float2 v1 = *(const float2*)(bufin + (size_t)s1 * 64 + lane * 2);
        float2 v2 = *(const float2*)(bufin + (size_t)s2 * 64 + lane * 2);
        float2 v3 = *(const float2*)(bufin + (size_t)s3 * 64 + lane * 2);
        float2 v4 = *(const float2*)(bufin + (size_t)s4 * 64 + lane * 2);
        float2 v5 = *(const float2*)(bufin + (size_t)s5 * 64 + lane * 2);
        float2 v6 = *(const float2*)(bufin + (size_t)s6 * 64 + lane * 2);
        float2 v7 = *(const float2*)(bufin + (size_t)s7 * 64 + lane * 2);
        a0.x += v0.x + v2.x + v4.x + v6.x;
        a0.y += v0.y + v2.y + v4.y + v6.y;
        a1.x += v1.x + v3.x + v5.x + v7.x;
        a1.y += v1.y + v3.y + v5.y + v7.y;
    }
    for (; j + 4 <= end; j += 4) {
        int s0 = __ldg(&g_csr[j]);
        int s1 = __ldg(&g_csr[j + 1]);
        int s2 = __ldg(&g_csr[j + 2]);
        int s3 = __ldg(&g_csr[j + 3]);
        float2 v0 = *(const float2*)(bufin + (size_t)s0 * 64 + lane * 2);
        float2 v1 = *(const float2*)(bufin + (size_t)s1 * 64 + lane * 2);
        float2 v2 = *(const float2*)(bufin + (size_t)s2 * 64 + lane * 2);
        float2 v3 = *(const float2*)(bufin + (size_t)s3 * 64 + lane * 2);
        a0.x += v0.x + v2.x; a0.y += v0.y + v2.y;
        a1.x += v1.x + v3.x; a1.y += v1.y + v3.y;
    }
    for (; j < end; j++) {
        int s0 = __ldg(&g_csr[j]);
        float2 v0 = *(const float2*)(bufin + (size_t)s0 * 64 + lane * 2);
        a0.x += v0.x; a0.y += v0.y;
    }
    a0.x += a1.x; a0.y += a1.y;
    float2 bb = *(const float2*)(bias + lane * 2);
    float r0 = fmaf(dd, a0.x, bb.x);
    float r1 = fmaf(dd, a0.y, bb.y);
    float2 ev; ev.x = r0; ev.y = r1;
    *(float2*)(e3 + (size_t)w * 64 + lane * 2) = ev;
    float mx = fmaxf(r0, r1);
    #pragma unroll
    for (int o = 16; o; o >>= 1) mx = fmaxf(mx, __shfl_xor_sync(0xffffffffu, mx, o));
    float sum = expf(r0 - mx) + expf(r1 - mx);
    #pragma unroll
    for (int o = 16; o; o >>= 1) sum += __shfl_xor_sync(0xffffffffu, sum, o);
    float lz = mx + logf(sum);
    float2 lp; lp.x = r0 - lz; lp.y = r1 - lz;
    *(float2*)(logp + (size_t)w * 64 + lane * 2) = lp;
}

// ---------------- launcher ------------------------------------------------------
extern "C" void kernel_launch(void* const* d_in, const int* in_sizes, int n_in,
                              void* d_out, int out_size) {
    const float* x  = (const float*)d_in[0];
    const void*  ed = d_in[1];
    const float* W1 = (const float*)d_in[2];
    const float* b1 = (const float*)d_in[3];
    const float* W2 = (const float*)d_in[4];
    const float* b2 = (const float*)d_in[5];
    const float* W3 = (const float*)d_in[6];
    const float* b3 = (const float*)d_in[7];

    int       N = in_sizes[0] / DF;
    long long E = (long long)in_sizes[1] / 2;

    float* out  = (float*)d_out;
    float* logp = out;
    float* e1   = out + (size_t)N * NC;
    float* e2   = e1 + (size_t)N * DF;
    float* e3   = e2 + (size_t)N * DF;

    float* bufA; cudaGetSymbolAddress((void**)&bufA, g_bufA);
    float* bufB; cudaGetSymbolAddress((void**)&bufB, g_bufB);

    const int smem128 = 2 * 128 * 272 + 2 * 64 * 272;  // 104448 -> 2 CTAs/SM
    const int smem64  = 2 * 64 * 272 + 2 * 64 * 272;   //  69632
    cudaFuncSetAttribute((const void*)k_hgemm<128, false>,
                         cudaFuncAttributeMaxDynamicSharedMemorySize, smem128);
    cudaFuncSetAttribute((const void*)k_fusedg<128>,
                         cudaFuncAttributeMaxDynamicSharedMemorySize, smem128);
    cudaFuncSetAttribute((const void*)k_fusedg<64>,
                         cudaFuncAttributeMaxDynamicSharedMemorySize, smem64);

    int nb_prep  = (16384 * 2 + 8192 + 255) / 256;
    int nb_edges = (int)((E + 255) / 256);
    int nb_fill  = (int)((E + 1023) / 1024);
    int nb_scan  = (N + 1023) / 1024;
    int nb_gemm  = (N + 63) / 64;
    int nb_gat   = (N + 7) / 8;

    // ---- CSR build + W prep; hgemm1 hoisted before fill (independent) ----
    k_prepw<<<nb_prep, 256>>>(ed, W1, W2, W3);
    k_count<<<nb_edges, 256>>>(ed, E);
    k_scanlb<<<nb_scan, 1024>>>(N, (int)E);
    k_hgemm<128, false><<<nb_gemm, 512, smem128>>>(x, bufA, 0, N);  // profile slot
    k_fill<<<nb_fill, 256>>>(ed, E);

    // ---- fused: gather1 (e1) + gemm W2 -> bufB ----
    k_fusedg<128><<<nb_gemm, 512, smem128>>>(bufA, bufB, b1, e1, 1, N);

    // ---- fused: gather2 (e2) + gemm W3 -> bufA (64-wide) ----
    k_fusedg<64><<<nb_gemm, 512, smem64>>>(bufB, bufA, b2, e2, 2, N);

    // ---- final gather + log_softmax ----
    k_gather64_lsm<<<nb_gat, 256>>>(bufA, b3, e3, logp, N);
}